// round 4
// baseline (speedup 1.0000x reference)
#include <cuda_runtime.h>
#include <cuda_bf16.h>
#include <cstdint>
#include <cstddef>

#define N_TOKENS 1024
#define IN_F 4096
#define OUT_F 4096
#define N_BLOCKS 512

#define TM 128
#define TN 256
#define KC 32
#define NKC (IN_F / KC)        // 128
#define STAGES 4
// stage: Ah 8K | Al 8K | Bh 16K | Bl 16K = 48KB
#define ST_AH 0
#define ST_AL 8192
#define ST_BH 16384
#define ST_BL 32768
#define STAGE_BYTES 49152
#define SMEM_TOTAL (STAGES * STAGE_BYTES)   // 192 KB

// ---------------- scratch (static device globals; no runtime allocation) ----
__device__ __nv_bfloat16 g_Xh[(size_t)N_TOKENS * IN_F];
__device__ __nv_bfloat16 g_Xl[(size_t)N_TOKENS * IN_F];
__device__ __nv_bfloat16 g_Wh[(size_t)OUT_F * IN_F];
__device__ __nv_bfloat16 g_Wl[(size_t)OUT_F * IN_F];

// ---------------- helpers ----------------------------------------------------
__device__ __forceinline__ uint32_t smem_u32(const void* p) {
    uint32_t a;
    asm("{ .reg .u64 t; cvta.to.shared.u64 t, %1; cvt.u32.u64 %0, t; }"
        : "=r"(a) : "l"(p));
    return a;
}

__device__ __forceinline__ uint32_t pack_bf2(__nv_bfloat16 a, __nv_bfloat16 b) {
    __nv_bfloat162 t = __halves2bfloat162(a, b);
    return *reinterpret_cast<uint32_t*>(&t);
}

__device__ __forceinline__ void cp16(uint32_t s, const void* g) {
    asm volatile("cp.async.cg.shared.global [%0], [%1], 16;"
                 :: "r"(s), "l"(g));
}

__device__ __forceinline__ void ldsm4(uint32_t* r, uint32_t a) {
    asm volatile("ldmatrix.sync.aligned.m8n8.x4.shared.b16 {%0,%1,%2,%3}, [%4];"
                 : "=r"(r[0]), "=r"(r[1]), "=r"(r[2]), "=r"(r[3]) : "r"(a));
}

__device__ __forceinline__ void mma16816(float* d, const uint32_t* a,
                                         const uint32_t* b) {
    asm volatile(
        "mma.sync.aligned.m16n8k16.row.col.f32.bf16.bf16.f32 "
        "{%0,%1,%2,%3}, {%4,%5,%6,%7}, {%8,%9}, {%0,%1,%2,%3};"
        : "+f"(d[0]), "+f"(d[1]), "+f"(d[2]), "+f"(d[3])
        : "r"(a[0]), "r"(a[1]), "r"(a[2]), "r"(a[3]), "r"(b[0]), "r"(b[1]));
}

// ---------------- kernel 1: fused prep (convert x  +  decode W) -------------
// blocks [0, 4096)            : split x into bf16 hi/lo (float4 per thread)
// blocks [4096, 4096 + 8192)  : decode quantized weights into bf16 hi/lo
#define PREP_X_BLOCKS 4096
#define PREP_W_BLOCKS 8192
__global__ void __launch_bounds__(256)
prep_kernel(const float* __restrict__ x,
            const float* __restrict__ centroids,
            const int* __restrict__ assignments) {
    if (blockIdx.x < PREP_X_BLOCKS) {
        int i = blockIdx.x * 256 + threadIdx.x;
        float4 v = reinterpret_cast<const float4*>(x)[i];
        __nv_bfloat16 h0 = __float2bfloat16(v.x), h1 = __float2bfloat16(v.y);
        __nv_bfloat16 h2 = __float2bfloat16(v.z), h3 = __float2bfloat16(v.w);
        __nv_bfloat16 l0 = __float2bfloat16(v.x - __bfloat162float(h0));
        __nv_bfloat16 l1 = __float2bfloat16(v.y - __bfloat162float(h1));
        __nv_bfloat16 l2 = __float2bfloat16(v.z - __bfloat162float(h2));
        __nv_bfloat16 l3 = __float2bfloat16(v.w - __bfloat162float(h3));
        uint2 uh; uh.x = pack_bf2(h0, h1); uh.y = pack_bf2(h2, h3);
        uint2 ul; ul.x = pack_bf2(l0, l1); ul.y = pack_bf2(l2, l3);
        reinterpret_cast<uint2*>(g_Xh)[i] = uh;
        reinterpret_cast<uint2*>(g_Xl)[i] = ul;
    } else {
        int idx = (blockIdx.x - PREP_X_BLOCKS) * 256 + threadIdx.x;
        int b = idx >> 12;            // idx / OUT_F
        int o = idx & (OUT_F - 1);    // idx % OUT_F
        int c = __ldg(&assignments[idx]);
        const float4* cp =
            reinterpret_cast<const float4*>(centroids + (size_t)c * 8);
        float4 v0 = cp[0];
        float4 v1 = cp[1];
        float f[8] = {v0.x, v0.y, v0.z, v0.w, v1.x, v1.y, v1.z, v1.w};
        __nv_bfloat16 h[8], l[8];
#pragma unroll
        for (int j = 0; j < 8; j++) {
            h[j] = __float2bfloat16(f[j]);
            l[j] = __float2bfloat16(f[j] - __bfloat162float(h[j]));
        }
        uint4 uh, ul;
        uh.x = pack_bf2(h[0], h[1]); uh.y = pack_bf2(h[2], h[3]);
        uh.z = pack_bf2(h[4], h[5]); uh.w = pack_bf2(h[6], h[7]);
        ul.x = pack_bf2(l[0], l[1]); ul.y = pack_bf2(l[2], l[3]);
        ul.z = pack_bf2(l[4], l[5]); ul.w = pack_bf2(l[6], l[7]);
        size_t w8 = ((size_t)o * IN_F + (size_t)b * 8) / 8;  // uint4 index
        reinterpret_cast<uint4*>(g_Wh)[w8] = uh;
        reinterpret_cast<uint4*>(g_Wl)[w8] = ul;
    }
}

// ---------------- kernel 2: mma.sync bf16x3 GEMM + bias ----------------------
// CTA tile 128x256, 8 warps in 2x4, warp tile 64x64.
// smem rows: 64B = 4 x 16B chunks; swizzle chunk' = chunk ^ ((row>>1)&3).
__global__ void __launch_bounds__(256, 1)
gemm_kernel(const float* __restrict__ bias, float* __restrict__ out) {
    extern __shared__ char smem[];
    uint32_t sb = smem_u32(smem);
    int tid = threadIdx.x, lane = tid & 31, wid = tid >> 5;
    int n0 = blockIdx.x * TN;
    int m0 = blockIdx.y * TM;
    int wm = (wid >> 2) * 64;   // warp M offset (0 / 64)
    int wn = (wid & 3) * 64;    // warp N offset (0..192)

    // ---- cp.async load mapping (256 threads, 12 chunks each) ----
    // A: 128 rows x 4 chunks x (h,l) = 1024 slots -> 4/thread
    // B: 256 rows x 4 chunks x (h,l) = 2048 slots -> 8/thread
    int arow = tid >> 1;                    // 0..127 (two threads per row)
    int ach = (tid & 1) * 2;                // chunks {0,1} or {2,3}
    uint32_t aoff0 = (uint32_t)(arow * 64 + (((ach + 0) ^ ((arow >> 1) & 3)) << 4));
    uint32_t aoff1 = (uint32_t)(arow * 64 + (((ach + 1) ^ ((arow >> 1) & 3)) << 4));
    const __nv_bfloat16* gAh = g_Xh + (size_t)(m0 + arow) * IN_F + ach * 8;
    const __nv_bfloat16* gAl = g_Xl + (size_t)(m0 + arow) * IN_F + ach * 8;

    int brow = tid;                          // 0..255, one row per thread
    int brs = (brow >> 1) & 3;
    uint32_t boff0 = (uint32_t)(brow * 64 + ((0 ^ brs) << 4));
    uint32_t boff1 = (uint32_t)(brow * 64 + ((1 ^ brs) << 4));
    uint32_t boff2 = (uint32_t)(brow * 64 + ((2 ^ brs) << 4));
    uint32_t boff3 = (uint32_t)(brow * 64 + ((3 ^ brs) << 4));
    const __nv_bfloat16* gBh = g_Wh + (size_t)(n0 + brow) * IN_F;
    const __nv_bfloat16* gBl = g_Wl + (size_t)(n0 + brow) * IN_F;

    // ---- ldmatrix fixed row indices ----
    int rA[4], rsA[4];
#pragma unroll
    for (int i = 0; i < 4; i++) {
        rA[i] = wm + i * 16 + (lane & 15);
        rsA[i] = (rA[i] >> 1) & 3;
    }
    int rB[4], rsB[4];
#pragma unroll
    for (int j2 = 0; j2 < 4; j2++) {
        rB[j2] = wn + j2 * 16 + ((lane >> 4) & 1) * 8 + (lane & 7);
        rsB[j2] = (rB[j2] >> 1) & 3;
    }
    int chA_lo = (lane >> 4);        // 0/1
    int chB_lo = ((lane >> 3) & 1);  // 0/1

    float acc[4][8][4];
#pragma unroll
    for (int i = 0; i < 4; i++)
#pragma unroll
        for (int j = 0; j < 8; j++)
#pragma unroll
            for (int e = 0; e < 4; e++) acc[i][j][e] = 0.f;

    // ---- prologue: fill STAGES-1 stages ----
#pragma unroll
    for (int s = 0; s < STAGES - 1; s++) {
        uint32_t st = sb + s * STAGE_BYTES;
        int k0 = s * KC;
        cp16(st + ST_AH + aoff0, gAh + k0);
        cp16(st + ST_AH + aoff1, gAh + k0 + 8);
        cp16(st + ST_AL + aoff0, gAl + k0);
        cp16(st + ST_AL + aoff1, gAl + k0 + 8);
        cp16(st + ST_BH + boff0, gBh + k0);
        cp16(st + ST_BH + boff1, gBh + k0 + 8);
        cp16(st + ST_BH + boff2, gBh + k0 + 16);
        cp16(st + ST_BH + boff3, gBh + k0 + 24);
        cp16(st + ST_BL + boff0, gBl + k0);
        cp16(st + ST_BL + boff1, gBl + k0 + 8);
        cp16(st + ST_BL + boff2, gBl + k0 + 16);
        cp16(st + ST_BL + boff3, gBl + k0 + 24);
        asm volatile("cp.async.commit_group;");
    }

    for (int kc = 0; kc < NKC; kc++) {
        asm volatile("cp.async.wait_group %0;" :: "n"(STAGES - 2));
        __syncthreads();
        uint32_t st = sb + (kc % STAGES) * STAGE_BYTES;

#pragma unroll
        for (int ks = 0; ks < 2; ks++) {
            uint32_t Ah[4][4], Al[4][4];
#pragma unroll
            for (int i = 0; i < 4; i++) {
                int ch = ks * 2 + chA_lo;
                uint32_t off = (uint32_t)(rA[i] * 64 + ((ch ^ rsA[i]) << 4));
                ldsm4(Ah[i], st + ST_AH + off);
                ldsm4(Al[i], st + ST_AL + off);
            }
#pragma unroll
            for (int j2 = 0; j2 < 4; j2++) {
                uint32_t Bh[4], Bl[4];
                int ch = ks * 2 + chB_lo;
                uint32_t off = (uint32_t)(rB[j2] * 64 + ((ch ^ rsB[j2]) << 4));
                ldsm4(Bh, st + ST_BH + off);
                ldsm4(Bl, st + ST_BL + off);
#pragma unroll
                for (int i = 0; i < 4; i++)
#pragma unroll
                    for (int jj = 0; jj < 2; jj++) {
                        float* d = acc[i][j2 * 2 + jj];
                        mma16816(d, Ah[i], &Bh[jj * 2]);
                        mma16816(d, Ah[i], &Bl[jj * 2]);
                        mma16816(d, Al[i], &Bh[jj * 2]);
                    }
            }
        }

        int nk = kc + STAGES - 1;
        if (nk < NKC) {
            uint32_t sn = sb + (nk % STAGES) * STAGE_BYTES;
            int k0 = nk * KC;
            cp16(sn + ST_AH + aoff0, gAh + k0);
            cp16(sn + ST_AH + aoff1, gAh + k0 + 8);
            cp16(sn + ST_AL + aoff0, gAl + k0);
            cp16(sn + ST_AL + aoff1, gAl + k0 + 8);
            cp16(sn + ST_BH + boff0, gBh + k0);
            cp16(sn + ST_BH + boff1, gBh + k0 + 8);
            cp16(sn + ST_BH + boff2, gBh + k0 + 16);
            cp16(sn + ST_BH + boff3, gBh + k0 + 24);
            cp16(sn + ST_BL + boff0, gBl + k0);
            cp16(sn + ST_BL + boff1, gBl + k0 + 8);
            cp16(sn + ST_BL + boff2, gBl + k0 + 16);
            cp16(sn + ST_BL + boff3, gBl + k0 + 24);
        }
        asm volatile("cp.async.commit_group;");
    }

    // ---- epilogue: bias add + fp32 stores ----
#pragma unroll
    for (int i = 0; i < 4; i++) {
        int r = m0 + wm + i * 16 + (lane >> 2);
        float* row0 = out + (size_t)r * OUT_F;
        float* row1 = row0 + (size_t)8 * OUT_F;
#pragma unroll
        for (int j = 0; j < 8; j++) {
            int c = n0 + wn + j * 8 + 2 * (lane & 3);
            float b0 = __ldg(&bias[c]), b1 = __ldg(&bias[c + 1]);
            float2 v0 = make_float2(acc[i][j][0] + b0, acc[i][j][1] + b1);
            float2 v1 = make_float2(acc[i][j][2] + b0, acc[i][j][3] + b1);
            *reinterpret_cast<float2*>(row0 + c) = v0;
            *reinterpret_cast<float2*>(row1 + c) = v1;
        }
    }
}

// ---------------- launch -----------------------------------------------------
extern "C" void kernel_launch(void* const* d_in, const int* in_sizes, int n_in,
                              void* d_out, int out_size) {
    const float* x           = (const float*)d_in[0];
    const float* centroids   = (const float*)d_in[1];
    const float* bias        = (const float*)d_in[2];
    const int*   assignments = (const int*)d_in[3];
    float* out = (float*)d_out;

    cudaFuncSetAttribute(gemm_kernel,
                         cudaFuncAttributeMaxDynamicSharedMemorySize, SMEM_TOTAL);

    prep_kernel<<<PREP_X_BLOCKS + PREP_W_BLOCKS, 256>>>(x, centroids, assignments);
    gemm_kernel<<<dim3(OUT_F / TN, N_TOKENS / TM), 256, SMEM_TOTAL>>>(bias, out);
}

// round 5
// speedup vs baseline: 1.1382x; 1.1382x over previous
#include <cuda_runtime.h>
#include <cuda_bf16.h>
#include <cstdint>
#include <cstddef>

#define N_TOKENS 1024
#define IN_F 4096
#define OUT_F 4096

#define TM 128
#define TN 256
#define KC 64
#define NKC (IN_F / KC)        // 64
// stage (96KB): AH[2] 16K | AL[2] 16K | BH[2] 32K | BL[2] 32K  (sub = 32-K half)
#define S_AH(sub) ((sub) * 8192)
#define S_AL(sub) (16384 + (sub) * 8192)
#define S_BH(sub) (32768 + (sub) * 16384)
#define S_BL(sub) (65536 + (sub) * 16384)
#define STAGE_BYTES 98304
#define SMEM_TOTAL (2 * STAGE_BYTES)   // 192 KB

// ---------------- scratch (static device globals; no runtime allocation) ----
__device__ __nv_bfloat16 g_Xh[(size_t)N_TOKENS * IN_F];
__device__ __nv_bfloat16 g_Xl[(size_t)N_TOKENS * IN_F];
__device__ __nv_bfloat16 g_Wh[(size_t)OUT_F * IN_F];
__device__ __nv_bfloat16 g_Wl[(size_t)OUT_F * IN_F];

// ---------------- helpers ----------------------------------------------------
__device__ __forceinline__ uint32_t smem_u32(const void* p) {
    uint32_t a;
    asm("{ .reg .u64 t; cvta.to.shared.u64 t, %1; cvt.u32.u64 %0, t; }"
        : "=r"(a) : "l"(p));
    return a;
}

__device__ __forceinline__ uint32_t pack_bf2(__nv_bfloat16 a, __nv_bfloat16 b) {
    __nv_bfloat162 t = __halves2bfloat162(a, b);
    return *reinterpret_cast<uint32_t*>(&t);
}

__device__ __forceinline__ void cp16(uint32_t s, const void* g) {
    asm volatile("cp.async.cg.shared.global [%0], [%1], 16;"
                 :: "r"(s), "l"(g));
}

__device__ __forceinline__ void ldsm4(uint32_t* r, uint32_t a) {
    asm volatile("ldmatrix.sync.aligned.m8n8.x4.shared.b16 {%0,%1,%2,%3}, [%4];"
                 : "=r"(r[0]), "=r"(r[1]), "=r"(r[2]), "=r"(r[3]) : "r"(a));
}

__device__ __forceinline__ void mma16816(float* d, const uint32_t* a,
                                         const uint32_t* b) {
    asm volatile(
        "mma.sync.aligned.m16n8k16.row.col.f32.bf16.bf16.f32 "
        "{%0,%1,%2,%3}, {%4,%5,%6,%7}, {%8,%9}, {%0,%1,%2,%3};"
        : "+f"(d[0]), "+f"(d[1]), "+f"(d[2]), "+f"(d[3])
        : "r"(a[0]), "r"(a[1]), "r"(a[2]), "r"(a[3]), "r"(b[0]), "r"(b[1]));
}

// ---------------- kernel 1: fused prep (convert x  +  decode W) -------------
#define PREP_X_BLOCKS 4096
#define PREP_W_BLOCKS 8192
__global__ void __launch_bounds__(256)
prep_kernel(const float* __restrict__ x,
            const float* __restrict__ centroids,
            const int* __restrict__ assignments) {
    if (blockIdx.x < PREP_X_BLOCKS) {
        int i = blockIdx.x * 256 + threadIdx.x;
        float4 v = reinterpret_cast<const float4*>(x)[i];
        __nv_bfloat16 h0 = __float2bfloat16(v.x), h1 = __float2bfloat16(v.y);
        __nv_bfloat16 h2 = __float2bfloat16(v.z), h3 = __float2bfloat16(v.w);
        __nv_bfloat16 l0 = __float2bfloat16(v.x - __bfloat162float(h0));
        __nv_bfloat16 l1 = __float2bfloat16(v.y - __bfloat162float(h1));
        __nv_bfloat16 l2 = __float2bfloat16(v.z - __bfloat162float(h2));
        __nv_bfloat16 l3 = __float2bfloat16(v.w - __bfloat162float(h3));
        uint2 uh; uh.x = pack_bf2(h0, h1); uh.y = pack_bf2(h2, h3);
        uint2 ul; ul.x = pack_bf2(l0, l1); ul.y = pack_bf2(l2, l3);
        reinterpret_cast<uint2*>(g_Xh)[i] = uh;
        reinterpret_cast<uint2*>(g_Xl)[i] = ul;
    } else {
        int idx = (blockIdx.x - PREP_X_BLOCKS) * 256 + threadIdx.x;
        int b = idx >> 12;
        int o = idx & (OUT_F - 1);
        int c = __ldg(&assignments[idx]);
        const float4* cp =
            reinterpret_cast<const float4*>(centroids + (size_t)c * 8);
        float4 v0 = cp[0];
        float4 v1 = cp[1];
        float f[8] = {v0.x, v0.y, v0.z, v0.w, v1.x, v1.y, v1.z, v1.w};
        __nv_bfloat16 h[8], l[8];
#pragma unroll
        for (int j = 0; j < 8; j++) {
            h[j] = __float2bfloat16(f[j]);
            l[j] = __float2bfloat16(f[j] - __bfloat162float(h[j]));
        }
        uint4 uh, ul;
        uh.x = pack_bf2(h[0], h[1]); uh.y = pack_bf2(h[2], h[3]);
        uh.z = pack_bf2(h[4], h[5]); uh.w = pack_bf2(h[6], h[7]);
        ul.x = pack_bf2(l[0], l[1]); ul.y = pack_bf2(l[2], l[3]);
        ul.z = pack_bf2(l[4], l[5]); ul.w = pack_bf2(l[6], l[7]);
        size_t w8 = ((size_t)o * IN_F + (size_t)b * 8) / 8;
        reinterpret_cast<uint4*>(g_Wh)[w8] = uh;
        reinterpret_cast<uint4*>(g_Wl)[w8] = ul;
    }
}

// ---------------- kernel 2: mma.sync bf16x3 GEMM + bias ----------------------
// CTA 128x256, 16 warps (4x4), warp tile 32x64. KC=64, 2-stage ping-pong.
// smem rows: 64B = 4 x 16B chunks; swizzle chunk' = chunk ^ ((row>>1)&3).
__global__ void __launch_bounds__(512, 1)
gemm_kernel(const float* __restrict__ bias, float* __restrict__ out) {
    extern __shared__ char smem[];
    uint32_t sb = smem_u32(smem);
    int tid = threadIdx.x, lane = tid & 31, wid = tid >> 5;
    int n0 = blockIdx.x * TN;
    int m0 = blockIdx.y * TM;
    int wm = (wid >> 2) * 32;   // warp M offset
    int wn = (wid & 3) * 64;    // warp N offset

    // ---- cp.async load mapping (512 threads, 12 x 16B each per stage) ----
    int arow = tid >> 2, ach = tid & 3;
    uint32_t aoff = (uint32_t)(arow * 64 + ((ach ^ ((arow >> 1) & 3)) << 4));
    const __nv_bfloat16* gAh = g_Xh + (size_t)(m0 + arow) * IN_F + ach * 8;
    const __nv_bfloat16* gAl = g_Xl + (size_t)(m0 + arow) * IN_F + ach * 8;

    int brow = tid >> 1, bch = (tid & 1) * 2;
    int brs = (brow >> 1) & 3;
    uint32_t boff0 = (uint32_t)(brow * 64 + (((bch + 0) ^ brs) << 4));
    uint32_t boff1 = (uint32_t)(brow * 64 + (((bch + 1) ^ brs) << 4));
    const __nv_bfloat16* gBh = g_Wh + (size_t)(n0 + brow) * IN_F + bch * 8;
    const __nv_bfloat16* gBl = g_Wl + (size_t)(n0 + brow) * IN_F + bch * 8;

    // ---- ldmatrix fixed row indices ----
    int rA[2], rsA[2];
#pragma unroll
    for (int i = 0; i < 2; i++) {
        rA[i] = wm + i * 16 + (lane & 15);
        rsA[i] = (rA[i] >> 1) & 3;
    }
    int rB[4], rsB[4];
#pragma unroll
    for (int j2 = 0; j2 < 4; j2++) {
        rB[j2] = wn + j2 * 16 + ((lane >> 4) & 1) * 8 + (lane & 7);
        rsB[j2] = (rB[j2] >> 1) & 3;
    }
    int chA_lo = (lane >> 4);        // 0/1
    int chB_lo = ((lane >> 3) & 1);  // 0/1

    float acc[2][8][4];
#pragma unroll
    for (int i = 0; i < 2; i++)
#pragma unroll
        for (int j = 0; j < 8; j++)
#pragma unroll
            for (int e = 0; e < 4; e++) acc[i][j][e] = 0.f;

    // ---- stage loader ----
    auto load_stage = [&](uint32_t st, int k0) {
#pragma unroll
        for (int sub = 0; sub < 2; sub++) {
            int ko = k0 + sub * 32;
            cp16(st + S_AH(sub) + aoff, gAh + ko);
            cp16(st + S_AL(sub) + aoff, gAl + ko);
            cp16(st + S_BH(sub) + boff0, gBh + ko);
            cp16(st + S_BH(sub) + boff1, gBh + ko + 8);
            cp16(st + S_BL(sub) + boff0, gBl + ko);
            cp16(st + S_BL(sub) + boff1, gBl + ko + 8);
        }
    };

    // ---- prologue: stage 0 ----
    load_stage(sb, 0);
    asm volatile("cp.async.commit_group;");

    for (int kc = 0; kc < NKC; kc++) {
        asm volatile("cp.async.wait_group 0;");
        __syncthreads();
        uint32_t st = sb + (kc & 1) * STAGE_BYTES;

        // issue next-stage loads right away (they complete during compute)
        if (kc + 1 < NKC)
            load_stage(sb + ((kc + 1) & 1) * STAGE_BYTES, (kc + 1) * KC);
        asm volatile("cp.async.commit_group;");

#pragma unroll
        for (int ks = 0; ks < 4; ks++) {
            int sub = ks >> 1, kk = ks & 1;
            uint32_t Ah[2][4], Al[2][4];
#pragma unroll
            for (int i = 0; i < 2; i++) {
                int ch = kk * 2 + chA_lo;
                uint32_t off = (uint32_t)(rA[i] * 64 + ((ch ^ rsA[i]) << 4));
                ldsm4(Ah[i], st + S_AH(sub) + off);
                ldsm4(Al[i], st + S_AL(sub) + off);
            }
#pragma unroll
            for (int j2 = 0; j2 < 4; j2++) {
                uint32_t Bh[4], Bl[4];
                int ch = kk * 2 + chB_lo;
                uint32_t off = (uint32_t)(rB[j2] * 64 + ((ch ^ rsB[j2]) << 4));
                ldsm4(Bh, st + S_BH(sub) + off);
                ldsm4(Bl, st + S_BL(sub) + off);
#pragma unroll
                for (int i = 0; i < 2; i++)
#pragma unroll
                    for (int jj = 0; jj < 2; jj++) {
                        float* d = acc[i][j2 * 2 + jj];
                        mma16816(d, Ah[i], &Bh[jj * 2]);
                        mma16816(d, Ah[i], &Bl[jj * 2]);
                        mma16816(d, Al[i], &Bh[jj * 2]);
                    }
            }
        }
    }

    // ---- epilogue: bias add + fp32 stores ----
#pragma unroll
    for (int i = 0; i < 2; i++) {
        int r = m0 + wm + i * 16 + (lane >> 2);
        float* row0 = out + (size_t)r * OUT_F;
        float* row1 = row0 + (size_t)8 * OUT_F;
#pragma unroll
        for (int j = 0; j < 8; j++) {
            int c = n0 + wn + j * 8 + 2 * (lane & 3);
            float b0 = __ldg(&bias[c]), b1 = __ldg(&bias[c + 1]);
            float2 v0 = make_float2(acc[i][j][0] + b0, acc[i][j][1] + b1);
            float2 v1 = make_float2(acc[i][j][2] + b0, acc[i][j][3] + b1);
            *reinterpret_cast<float2*>(row0 + c) = v0;
            *reinterpret_cast<float2*>(row1 + c) = v1;
        }
    }
}

// ---------------- launch -----------------------------------------------------
extern "C" void kernel_launch(void* const* d_in, const int* in_sizes, int n_in,
                              void* d_out, int out_size) {
    const float* x           = (const float*)d_in[0];
    const float* centroids   = (const float*)d_in[1];
    const float* bias        = (const float*)d_in[2];
    const int*   assignments = (const int*)d_in[3];
    float* out = (float*)d_out;

    cudaFuncSetAttribute(gemm_kernel,
                         cudaFuncAttributeMaxDynamicSharedMemorySize, SMEM_TOTAL);

    prep_kernel<<<PREP_X_BLOCKS + PREP_W_BLOCKS, 256>>>(x, centroids, assignments);
    gemm_kernel<<<dim3(OUT_F / TN, N_TOKENS / TM), 512, SMEM_TOTAL>>>(bias, out);
}

// round 6
// speedup vs baseline: 1.1398x; 1.0014x over previous
#include <cuda_runtime.h>
#include <cuda_bf16.h>
#include <cstdint>
#include <cstddef>

#define N_TOKENS 1024
#define IN_F 4096
#define OUT_F 4096

#define TM 128
#define TN 256
#define KC 64
#define NKC (IN_F / KC)        // 64
// stage (96KB): AH[2] 16K | AL[2] 16K | BH[2] 32K | BL[2] 32K  (sub = 32-K half)
#define S_AH(sub) ((sub) * 8192)
#define S_AL(sub) (16384 + (sub) * 8192)
#define S_BH(sub) (32768 + (sub) * 16384)
#define S_BL(sub) (65536 + (sub) * 16384)
#define STAGE_BYTES 98304
#define SMEM_TOTAL (2 * STAGE_BYTES)   // 192 KB

// ---------------- scratch (static device globals; no runtime allocation) ----
__device__ __nv_bfloat16 g_Xh[(size_t)N_TOKENS * IN_F];
__device__ __nv_bfloat16 g_Xl[(size_t)N_TOKENS * IN_F];
__device__ __nv_bfloat16 g_Wh[(size_t)OUT_F * IN_F];
__device__ __nv_bfloat16 g_Wl[(size_t)OUT_F * IN_F];

// ---------------- helpers ----------------------------------------------------
__device__ __forceinline__ uint32_t smem_u32(const void* p) {
    uint32_t a;
    asm("{ .reg .u64 t; cvta.to.shared.u64 t, %1; cvt.u32.u64 %0, t; }"
        : "=r"(a) : "l"(p));
    return a;
}

__device__ __forceinline__ uint32_t pack_bf2(__nv_bfloat16 a, __nv_bfloat16 b) {
    __nv_bfloat162 t = __halves2bfloat162(a, b);
    return *reinterpret_cast<uint32_t*>(&t);
}

__device__ __forceinline__ void cp16(uint32_t s, const void* g) {
    asm volatile("cp.async.cg.shared.global [%0], [%1], 16;"
                 :: "r"(s), "l"(g));
}

__device__ __forceinline__ void ldsm4(uint32_t* r, uint32_t a) {
    asm volatile("ldmatrix.sync.aligned.m8n8.x4.shared.b16 {%0,%1,%2,%3}, [%4];"
                 : "=r"(r[0]), "=r"(r[1]), "=r"(r[2]), "=r"(r[3]) : "r"(a));
}

__device__ __forceinline__ void mma16816(float* d, const uint32_t* a,
                                         const uint32_t* b) {
    asm volatile(
        "mma.sync.aligned.m16n8k16.row.col.f32.bf16.bf16.f32 "
        "{%0,%1,%2,%3}, {%4,%5,%6,%7}, {%8,%9}, {%0,%1,%2,%3};"
        : "+f"(d[0]), "+f"(d[1]), "+f"(d[2]), "+f"(d[3])
        : "r"(a[0]), "r"(a[1]), "r"(a[2]), "r"(a[3]), "r"(b[0]), "r"(b[1]));
}

// ---------------- kernel 1: fused prep (convert x  +  decode W) -------------
#define PREP_X_BLOCKS 4096
#define PREP_W_BLOCKS 8192
__global__ void __launch_bounds__(256)
prep_kernel(const float* __restrict__ x,
            const float* __restrict__ centroids,
            const int* __restrict__ assignments) {
    if (blockIdx.x < PREP_X_BLOCKS) {
        int i = blockIdx.x * 256 + threadIdx.x;
        float4 v = reinterpret_cast<const float4*>(x)[i];
        __nv_bfloat16 h0 = __float2bfloat16(v.x), h1 = __float2bfloat16(v.y);
        __nv_bfloat16 h2 = __float2bfloat16(v.z), h3 = __float2bfloat16(v.w);
        __nv_bfloat16 l0 = __float2bfloat16(v.x - __bfloat162float(h0));
        __nv_bfloat16 l1 = __float2bfloat16(v.y - __bfloat162float(h1));
        __nv_bfloat16 l2 = __float2bfloat16(v.z - __bfloat162float(h2));
        __nv_bfloat16 l3 = __float2bfloat16(v.w - __bfloat162float(h3));
        uint2 uh; uh.x = pack_bf2(h0, h1); uh.y = pack_bf2(h2, h3);
        uint2 ul; ul.x = pack_bf2(l0, l1); ul.y = pack_bf2(l2, l3);
        reinterpret_cast<uint2*>(g_Xh)[i] = uh;
        reinterpret_cast<uint2*>(g_Xl)[i] = ul;
    } else {
        int idx = (blockIdx.x - PREP_X_BLOCKS) * 256 + threadIdx.x;
        int b = idx >> 12;
        int o = idx & (OUT_F - 1);
        int c = __ldg(&assignments[idx]);
        const float4* cp =
            reinterpret_cast<const float4*>(centroids + (size_t)c * 8);
        float4 v0 = cp[0];
        float4 v1 = cp[1];
        float f[8] = {v0.x, v0.y, v0.z, v0.w, v1.x, v1.y, v1.z, v1.w};
        __nv_bfloat16 h[8], l[8];
#pragma unroll
        for (int j = 0; j < 8; j++) {
            h[j] = __float2bfloat16(f[j]);
            l[j] = __float2bfloat16(f[j] - __bfloat162float(h[j]));
        }
        uint4 uh, ul;
        uh.x = pack_bf2(h[0], h[1]); uh.y = pack_bf2(h[2], h[3]);
        uh.z = pack_bf2(h[4], h[5]); uh.w = pack_bf2(h[6], h[7]);
        ul.x = pack_bf2(l[0], l[1]); ul.y = pack_bf2(l[2], l[3]);
        ul.z = pack_bf2(l[4], l[5]); ul.w = pack_bf2(l[6], l[7]);
        size_t w8 = ((size_t)o * IN_F + (size_t)b * 8) / 8;
        reinterpret_cast<uint4*>(g_Wh)[w8] = uh;
        reinterpret_cast<uint4*>(g_Wl)[w8] = ul;
    }
}

// ---------------- kernel 2: mma.sync bf16x3 GEMM + bias ----------------------
// CTA 128x256, 16 warps (4x4), warp tile 32x64. KC=64, 2-stage ping-pong.
// smem rows: 64B = 4 x 16B chunks; swizzle chunk' = chunk ^ ((row>>1)&3).
__global__ void __launch_bounds__(512, 1)
gemm_kernel(const float* __restrict__ bias, float* __restrict__ out) {
    extern __shared__ char smem[];
    uint32_t sb = smem_u32(smem);
    int tid = threadIdx.x, lane = tid & 31, wid = tid >> 5;
    int n0 = blockIdx.x * TN;
    int m0 = blockIdx.y * TM;
    int wm = (wid >> 2) * 32;   // warp M offset
    int wn = (wid & 3) * 64;    // warp N offset

    // ---- cp.async load mapping (512 threads, 12 x 16B each per stage) ----
    int arow = tid >> 2, ach = tid & 3;
    uint32_t aoff = (uint32_t)(arow * 64 + ((ach ^ ((arow >> 1) & 3)) << 4));
    const __nv_bfloat16* gAh = g_Xh + (size_t)(m0 + arow) * IN_F + ach * 8;
    const __nv_bfloat16* gAl = g_Xl + (size_t)(m0 + arow) * IN_F + ach * 8;

    int brow = tid >> 1, bch = (tid & 1) * 2;
    int brs = (brow >> 1) & 3;
    uint32_t boff0 = (uint32_t)(brow * 64 + (((bch + 0) ^ brs) << 4));
    uint32_t boff1 = (uint32_t)(brow * 64 + (((bch + 1) ^ brs) << 4));
    const __nv_bfloat16* gBh = g_Wh + (size_t)(n0 + brow) * IN_F + bch * 8;
    const __nv_bfloat16* gBl = g_Wl + (size_t)(n0 + brow) * IN_F + bch * 8;

    // ---- ldmatrix fixed row indices ----
    int rA[2], rsA[2];
#pragma unroll
    for (int i = 0; i < 2; i++) {
        rA[i] = wm + i * 16 + (lane & 15);
        rsA[i] = (rA[i] >> 1) & 3;
    }
    int rB[4], rsB[4];
#pragma unroll
    for (int j2 = 0; j2 < 4; j2++) {
        rB[j2] = wn + j2 * 16 + ((lane >> 4) & 1) * 8 + (lane & 7);
        rsB[j2] = (rB[j2] >> 1) & 3;
    }
    int chA_lo = (lane >> 4);        // 0/1
    int chB_lo = ((lane >> 3) & 1);  // 0/1

    float acc[2][8][4];
#pragma unroll
    for (int i = 0; i < 2; i++)
#pragma unroll
        for (int j = 0; j < 8; j++)
#pragma unroll
            for (int e = 0; e < 4; e++) acc[i][j][e] = 0.f;

    // ---- stage loader ----
    auto load_stage = [&](uint32_t st, int k0) {
#pragma unroll
        for (int sub = 0; sub < 2; sub++) {
            int ko = k0 + sub * 32;
            cp16(st + S_AH(sub) + aoff, gAh + ko);
            cp16(st + S_AL(sub) + aoff, gAl + ko);
            cp16(st + S_BH(sub) + boff0, gBh + ko);
            cp16(st + S_BH(sub) + boff1, gBh + ko + 8);
            cp16(st + S_BL(sub) + boff0, gBl + ko);
            cp16(st + S_BL(sub) + boff1, gBl + ko + 8);
        }
    };

    // ---- prologue: stage 0 ----
    load_stage(sb, 0);
    asm volatile("cp.async.commit_group;");

    for (int kc = 0; kc < NKC; kc++) {
        asm volatile("cp.async.wait_group 0;");
        __syncthreads();
        uint32_t st = sb + (kc & 1) * STAGE_BYTES;

        // issue next-stage loads right away (they complete during compute)
        if (kc + 1 < NKC)
            load_stage(sb + ((kc + 1) & 1) * STAGE_BYTES, (kc + 1) * KC);
        asm volatile("cp.async.commit_group;");

#pragma unroll
        for (int ks = 0; ks < 4; ks++) {
            int sub = ks >> 1, kk = ks & 1;
            uint32_t Ah[2][4], Al[2][4];
#pragma unroll
            for (int i = 0; i < 2; i++) {
                int ch = kk * 2 + chA_lo;
                uint32_t off = (uint32_t)(rA[i] * 64 + ((ch ^ rsA[i]) << 4));
                ldsm4(Ah[i], st + S_AH(sub) + off);
                ldsm4(Al[i], st + S_AL(sub) + off);
            }
#pragma unroll
            for (int j2 = 0; j2 < 4; j2++) {
                uint32_t Bh[4], Bl[4];
                int ch = kk * 2 + chB_lo;
                uint32_t off = (uint32_t)(rB[j2] * 64 + ((ch ^ rsB[j2]) << 4));
                ldsm4(Bh, st + S_BH(sub) + off);
                ldsm4(Bl, st + S_BL(sub) + off);
#pragma unroll
                for (int i = 0; i < 2; i++)
#pragma unroll
                    for (int jj = 0; jj < 2; jj++) {
                        float* d = acc[i][j2 * 2 + jj];
                        mma16816(d, Ah[i], &Bh[jj * 2]);
                        mma16816(d, Ah[i], &Bl[jj * 2]);
                        mma16816(d, Al[i], &Bh[jj * 2]);
                    }
            }
        }
    }

    // ---- epilogue: bias add + fp32 stores ----
#pragma unroll
    for (int i = 0; i < 2; i++) {
        int r = m0 + wm + i * 16 + (lane >> 2);
        float* row0 = out + (size_t)r * OUT_F;
        float* row1 = row0 + (size_t)8 * OUT_F;
#pragma unroll
        for (int j = 0; j < 8; j++) {
            int c = n0 + wn + j * 8 + 2 * (lane & 3);
            float b0 = __ldg(&bias[c]), b1 = __ldg(&bias[c + 1]);
            float2 v0 = make_float2(acc[i][j][0] + b0, acc[i][j][1] + b1);
            float2 v1 = make_float2(acc[i][j][2] + b0, acc[i][j][3] + b1);
            *reinterpret_cast<float2*>(row0 + c) = v0;
            *reinterpret_cast<float2*>(row1 + c) = v1;
        }
    }
}

// ---------------- launch -----------------------------------------------------
extern "C" void kernel_launch(void* const* d_in, const int* in_sizes, int n_in,
                              void* d_out, int out_size) {
    const float* x           = (const float*)d_in[0];
    const float* centroids   = (const float*)d_in[1];
    const float* bias        = (const float*)d_in[2];
    const int*   assignments = (const int*)d_in[3];
    float* out = (float*)d_out;

    cudaFuncSetAttribute(gemm_kernel,
                         cudaFuncAttributeMaxDynamicSharedMemorySize, SMEM_TOTAL);

    prep_kernel<<<PREP_X_BLOCKS + PREP_W_BLOCKS, 256>>>(x, centroids, assignments);
    gemm_kernel<<<dim3(OUT_F / TN, N_TOKENS / TM), 512, SMEM_TOTAL>>>(bias, out);
}

// round 7
// speedup vs baseline: 1.3612x; 1.1943x over previous
#include <cuda_runtime.h>
#include <cuda_bf16.h>
#include <cstdint>
#include <cstddef>

#define N_TOKENS 1024
#define IN_F 4096
#define OUT_F 4096
#define N_BLOCKS 512

#define TM 128
#define TN 256
#define KC 32
#define NKC (IN_F / KC)        // 128
#define STAGES 4
// stage: Ah 8K | Al 8K | Bh 16K | Bl 16K = 48KB
#define ST_AH 0
#define ST_AL 8192
#define ST_BH 16384
#define ST_BL 32768
#define STAGE_BYTES 49152
#define SMEM_TOTAL (STAGES * STAGE_BYTES)   // 192 KB

// ---------------- scratch (static device globals; no runtime allocation) ----
// X: row-major [token][k].  W: BLOCK-MAJOR [b][o][8] so both the decode writes
// and the GEMM B-tile reads are fully coalesced (16B chunk index = b*4096+o).
__device__ __nv_bfloat16 g_Xh[(size_t)N_TOKENS * IN_F];
__device__ __nv_bfloat16 g_Xl[(size_t)N_TOKENS * IN_F];
__device__ __nv_bfloat16 g_Wh[(size_t)OUT_F * IN_F];
__device__ __nv_bfloat16 g_Wl[(size_t)OUT_F * IN_F];

// ---------------- helpers ----------------------------------------------------
__device__ __forceinline__ uint32_t smem_u32(const void* p) {
    uint32_t a;
    asm("{ .reg .u64 t; cvta.to.shared.u64 t, %1; cvt.u32.u64 %0, t; }"
        : "=r"(a) : "l"(p));
    return a;
}

__device__ __forceinline__ uint32_t pack_bf2(__nv_bfloat16 a, __nv_bfloat16 b) {
    __nv_bfloat162 t = __halves2bfloat162(a, b);
    return *reinterpret_cast<uint32_t*>(&t);
}

__device__ __forceinline__ void cp16(uint32_t s, const void* g) {
    asm volatile("cp.async.cg.shared.global [%0], [%1], 16;"
                 :: "r"(s), "l"(g));
}

__device__ __forceinline__ void ldsm4(uint32_t* r, uint32_t a) {
    asm volatile("ldmatrix.sync.aligned.m8n8.x4.shared.b16 {%0,%1,%2,%3}, [%4];"
                 : "=r"(r[0]), "=r"(r[1]), "=r"(r[2]), "=r"(r[3]) : "r"(a));
}

__device__ __forceinline__ void mma16816(float* d, const uint32_t* a,
                                         const uint32_t* b) {
    asm volatile(
        "mma.sync.aligned.m16n8k16.row.col.f32.bf16.bf16.f32 "
        "{%0,%1,%2,%3}, {%4,%5,%6,%7}, {%8,%9}, {%0,%1,%2,%3};"
        : "+f"(d[0]), "+f"(d[1]), "+f"(d[2]), "+f"(d[3])
        : "r"(a[0]), "r"(a[1]), "r"(a[2]), "r"(a[3]), "r"(b[0]), "r"(b[1]));
}

// ---------------- kernel 1: fused prep (convert x  +  decode W) -------------
#define PREP_X_BLOCKS 4096
#define PREP_W_BLOCKS 8192
__global__ void __launch_bounds__(256)
prep_kernel(const float* __restrict__ x,
            const float* __restrict__ centroids,
            const int* __restrict__ assignments) {
    if (blockIdx.x < PREP_X_BLOCKS) {
        int i = blockIdx.x * 256 + threadIdx.x;
        float4 v = reinterpret_cast<const float4*>(x)[i];
        __nv_bfloat16 h0 = __float2bfloat16(v.x), h1 = __float2bfloat16(v.y);
        __nv_bfloat16 h2 = __float2bfloat16(v.z), h3 = __float2bfloat16(v.w);
        __nv_bfloat16 l0 = __float2bfloat16(v.x - __bfloat162float(h0));
        __nv_bfloat16 l1 = __float2bfloat16(v.y - __bfloat162float(h1));
        __nv_bfloat16 l2 = __float2bfloat16(v.z - __bfloat162float(h2));
        __nv_bfloat16 l3 = __float2bfloat16(v.w - __bfloat162float(h3));
        uint2 uh; uh.x = pack_bf2(h0, h1); uh.y = pack_bf2(h2, h3);
        uint2 ul; ul.x = pack_bf2(l0, l1); ul.y = pack_bf2(l2, l3);
        reinterpret_cast<uint2*>(g_Xh)[i] = uh;
        reinterpret_cast<uint2*>(g_Xl)[i] = ul;
    } else {
        int idx = (blockIdx.x - PREP_X_BLOCKS) * 256 + threadIdx.x;
        // idx = b*4096 + o; write chunk idx of block-major W -> coalesced
        int c = __ldg(&assignments[idx]);
        const float4* cp =
            reinterpret_cast<const float4*>(centroids + (size_t)c * 8);
        float4 v0 = cp[0];
        float4 v1 = cp[1];
        float f[8] = {v0.x, v0.y, v0.z, v0.w, v1.x, v1.y, v1.z, v1.w};
        __nv_bfloat16 h[8], l[8];
#pragma unroll
        for (int j = 0; j < 8; j++) {
            h[j] = __float2bfloat16(f[j]);
            l[j] = __float2bfloat16(f[j] - __bfloat162float(h[j]));
        }
        uint4 uh, ul;
        uh.x = pack_bf2(h[0], h[1]); uh.y = pack_bf2(h[2], h[3]);
        uh.z = pack_bf2(h[4], h[5]); uh.w = pack_bf2(h[6], h[7]);
        ul.x = pack_bf2(l[0], l[1]); ul.y = pack_bf2(l[2], l[3]);
        ul.z = pack_bf2(l[4], l[5]); ul.w = pack_bf2(l[6], l[7]);
        reinterpret_cast<uint4*>(g_Wh)[idx] = uh;
        reinterpret_cast<uint4*>(g_Wl)[idx] = ul;
    }
}

// ---------------- kernel 2: mma.sync bf16x3 GEMM + bias ----------------------
// CTA tile 128x256, 16 warps 4x4, warp tile 32x64, 4-stage cp.async.
// smem rows: 64B = 4 x 16B chunks; swizzle chunk' = chunk ^ ((row>>1)&3).
__global__ void __launch_bounds__(512, 1)
gemm_kernel(const float* __restrict__ bias, float* __restrict__ out) {
    extern __shared__ char smem[];
    uint32_t sb = smem_u32(smem);
    int tid = threadIdx.x, lane = tid & 31, wid = tid >> 5;
    int n0 = blockIdx.x * TN;
    int m0 = blockIdx.y * TM;
    int wm = (wid >> 2) * 32;   // warp M offset
    int wn = (wid & 3) * 64;    // warp N offset

    // ---- cp.async load mapping ----
    int arow = tid >> 2, ach = tid & 3;
    uint32_t aoff = (uint32_t)(arow * 64 + ((ach ^ ((arow >> 1) & 3)) << 4));
    const __nv_bfloat16* gAh = g_Xh + (size_t)(m0 + arow) * IN_F + ach * 8;
    const __nv_bfloat16* gAl = g_Xl + (size_t)(m0 + arow) * IN_F + ach * 8;

    // B block-major: chunk (block b, row o) at element ((size_t)b*OUT_F + o)*8.
    // Each thread: rows brow0=arow, brow1=arow+128, block = k0/8 + ach.
    int brow1 = arow + 128;
    uint32_t boff0 = aoff;
    uint32_t boff1 = (uint32_t)(brow1 * 64 + ((ach ^ ((brow1 >> 1) & 3)) << 4));
    size_t bbase0 = (size_t)ach * OUT_F + (n0 + arow);    // chunk idx at k0=0
    size_t bbase1 = (size_t)ach * OUT_F + (n0 + brow1);

    // ---- ldmatrix fixed row indices ----
    int rA[2], rsA[2];
#pragma unroll
    for (int i = 0; i < 2; i++) {
        rA[i] = wm + i * 16 + (lane & 15);
        rsA[i] = (rA[i] >> 1) & 3;
    }
    int rB[4], rsB[4];
#pragma unroll
    for (int j2 = 0; j2 < 4; j2++) {
        rB[j2] = wn + j2 * 16 + ((lane >> 4) & 1) * 8 + (lane & 7);
        rsB[j2] = (rB[j2] >> 1) & 3;
    }
    int chA_lo = (lane >> 4);        // 0/1
    int chB_lo = ((lane >> 3) & 1);  // 0/1

    float acc[2][8][4];
#pragma unroll
    for (int i = 0; i < 2; i++)
#pragma unroll
        for (int j = 0; j < 8; j++)
#pragma unroll
            for (int e = 0; e < 4; e++) acc[i][j][e] = 0.f;

    auto load_stage = [&](uint32_t st, int kc) {
        int k0 = kc * KC;
        size_t bi0 = bbase0 + (size_t)(kc * 4) * OUT_F;  // 4 blocks per KC
        size_t bi1 = bbase1 + (size_t)(kc * 4) * OUT_F;
        cp16(st + ST_AH + aoff, gAh + k0);
        cp16(st + ST_AL + aoff, gAl + k0);
        cp16(st + ST_BH + boff0, reinterpret_cast<const uint4*>(g_Wh) + bi0);
        cp16(st + ST_BH + boff1, reinterpret_cast<const uint4*>(g_Wh) + bi1);
        cp16(st + ST_BL + boff0, reinterpret_cast<const uint4*>(g_Wl) + bi0);
        cp16(st + ST_BL + boff1, reinterpret_cast<const uint4*>(g_Wl) + bi1);
        asm volatile("cp.async.commit_group;");
    };

    // ---- prologue: fill STAGES-1 stages ----
#pragma unroll
    for (int s = 0; s < STAGES - 1; s++)
        load_stage(sb + s * STAGE_BYTES, s);

    for (int kc = 0; kc < NKC; kc++) {
        asm volatile("cp.async.wait_group %0;" :: "n"(STAGES - 2));
        __syncthreads();
        uint32_t st = sb + (kc % STAGES) * STAGE_BYTES;

#pragma unroll
        for (int ks = 0; ks < 2; ks++) {
            uint32_t Ah[2][4], Al[2][4];
#pragma unroll
            for (int i = 0; i < 2; i++) {
                int ch = ks * 2 + chA_lo;
                uint32_t off = (uint32_t)(rA[i] * 64 + ((ch ^ rsA[i]) << 4));
                ldsm4(Ah[i], st + ST_AH + off);
                ldsm4(Al[i], st + ST_AL + off);
            }
#pragma unroll
            for (int j2 = 0; j2 < 4; j2++) {
                uint32_t Bh[4], Bl[4];
                int ch = ks * 2 + chB_lo;
                uint32_t off = (uint32_t)(rB[j2] * 64 + ((ch ^ rsB[j2]) << 4));
                ldsm4(Bh, st + ST_BH + off);
                ldsm4(Bl, st + ST_BL + off);
                float* d00 = acc[0][j2 * 2];
                float* d01 = acc[0][j2 * 2 + 1];
                float* d10 = acc[1][j2 * 2];
                float* d11 = acc[1][j2 * 2 + 1];
                // term-major: same-accumulator reuse distance = 4 MMAs
                mma16816(d00, Ah[0], &Bh[0]);
                mma16816(d01, Ah[0], &Bh[2]);
                mma16816(d10, Ah[1], &Bh[0]);
                mma16816(d11, Ah[1], &Bh[2]);
                mma16816(d00, Ah[0], &Bl[0]);
                mma16816(d01, Ah[0], &Bl[2]);
                mma16816(d10, Ah[1], &Bl[0]);
                mma16816(d11, Ah[1], &Bl[2]);
                mma16816(d00, Al[0], &Bh[0]);
                mma16816(d01, Al[0], &Bh[2]);
                mma16816(d10, Al[1], &Bh[0]);
                mma16816(d11, Al[1], &Bh[2]);
            }
        }

        int nk = kc + STAGES - 1;
        if (nk < NKC)
            load_stage(sb + (nk % STAGES) * STAGE_BYTES, nk);
        else
            asm volatile("cp.async.commit_group;");
    }

    // ---- epilogue: bias add + fp32 stores ----
#pragma unroll
    for (int i = 0; i < 2; i++) {
        int r = m0 + wm + i * 16 + (lane >> 2);
        float* row0 = out + (size_t)r * OUT_F;
        float* row1 = row0 + (size_t)8 * OUT_F;
#pragma unroll
        for (int j = 0; j < 8; j++) {
            int c = n0 + wn + j * 8 + 2 * (lane & 3);
            float b0 = __ldg(&bias[c]), b1 = __ldg(&bias[c + 1]);
            float2 v0 = make_float2(acc[i][j][0] + b0, acc[i][j][1] + b1);
            float2 v1 = make_float2(acc[i][j][2] + b0, acc[i][j][3] + b1);
            *reinterpret_cast<float2*>(row0 + c) = v0;
            *reinterpret_cast<float2*>(row1 + c) = v1;
        }
    }
}

// ---------------- launch -----------------------------------------------------
extern "C" void kernel_launch(void* const* d_in, const int* in_sizes, int n_in,
                              void* d_out, int out_size) {
    const float* x           = (const float*)d_in[0];
    const float* centroids   = (const float*)d_in[1];
    const float* bias        = (const float*)d_in[2];
    const int*   assignments = (const int*)d_in[3];
    float* out = (float*)d_out;

    cudaFuncSetAttribute(gemm_kernel,
                         cudaFuncAttributeMaxDynamicSharedMemorySize, SMEM_TOTAL);

    prep_kernel<<<PREP_X_BLOCKS + PREP_W_BLOCKS, 256>>>(x, centroids, assignments);
    gemm_kernel<<<dim3(OUT_F / TN, N_TOKENS / TM), 512, SMEM_TOTAL>>>(bias, out);
}